// round 10
// baseline (speedup 1.0000x reference)
#include <cuda_runtime.h>
#include <cuda_bf16.h>

// NLL sequence loss: only the last valid timestep per batch row contributes.
//   loss = -(1/B) * sum_b inputs[b, min(T,length[b])-1, target[b]]
//
// CONVERGED FINAL FORM. This exact binary measured 6.624 / 6.880 / 6.304 /
// 6.624 us across four consecutive rounds (R6-R9): same-artifact bench noise
// is +/-0.3us around a ~6.6us graph-replay/launch floor. The warm kernel
// body is ~0.3us (one vectorized index-load round -> one fully-overlapped
// dependent gather round -> ~150cyc reduction tail). No in-kernel change can
// produce a delta above the noise floor; the remaining 6+us is harness
// overhead outside kernel_launch's control. All ncu pipes <=0.2% — no
// hardware roofline applies to 4KB of useful traffic.
//
// 4 warps x 4 rows/thread:
//  - length/target read as one int4 per array per thread.
//  - 4 independent gathers per thread; all 512 gathers overlap in a single
//    L2/DRAM latency round chip-wide (irreducible: data-dependent addresses).
//  - Reduction: 3 register adds -> 5 warp shuffles -> 4 smem words -> one
//    thread does 3 adds + negate-scale multiply + store.

#define B_DIM 512
#define T_DIM 128
#define C_DIM 2000
#define NTHREADS 128
#define RPT 4   // rows per thread = B_DIM / NTHREADS
#define NWARPS (NTHREADS / 32)

__global__ __launch_bounds__(NTHREADS, 1)
void nll_seq_loss_kernel(const float* __restrict__ inputs,
                         const int*   __restrict__ length,
                         const int*   __restrict__ target,
                         float*       __restrict__ out) {
    const int t = threadIdx.x;
    const int base = t * RPT;   // contiguous 4-row chunk -> aligned int4

    int4 l = *(const int4*)(length + base);
    int4 g = *(const int4*)(target + base);

    int len[RPT] = {l.x, l.y, l.z, l.w};
    int tgt[RPT] = {g.x, g.y, g.z, g.w};

    float v[RPT];
    #pragma unroll
    for (int j = 0; j < RPT; j++) {
        int last = (len[j] < T_DIM ? len[j] : T_DIM) - 1;
        int idx = ((base + j) * T_DIM + last) * C_DIM + tgt[j];
        v[j] = __ldg(inputs + idx);
    }

    float s = (v[0] + v[1]) + (v[2] + v[3]);

    #pragma unroll
    for (int off = 16; off > 0; off >>= 1)
        s += __shfl_down_sync(0xFFFFFFFFu, s, off);

    __shared__ float warp_sums[NWARPS];
    const int lane = t & 31;
    const int wid  = t >> 5;
    if (lane == 0) warp_sums[wid] = s;
    __syncthreads();

    if (t == 0) {
        float w = (warp_sums[0] + warp_sums[1]) + (warp_sums[2] + warp_sums[3]);
        out[0] = w * (-1.0f / (float)B_DIM);
    }
}

extern "C" void kernel_launch(void* const* d_in, const int* in_sizes, int n_in,
                              void* d_out, int out_size) {
    const float* inputs = (const float*)d_in[0];
    const int*   length = (const int*)d_in[1];
    const int*   target = (const int*)d_in[2];
    float*       out    = (float*)d_out;

    nll_seq_loss_kernel<<<1, NTHREADS>>>(inputs, length, target, out);
}

// round 11
// speedup vs baseline: 1.0048x; 1.0048x over previous
#include <cuda_runtime.h>
#include <cuda_bf16.h>

// NLL sequence loss: only the last valid timestep per batch row contributes.
//   loss = -(1/B) * sum_b inputs[b, min(T,length[b])-1, target[b]]
//
// CONVERGED FINAL FORM. This exact binary measured 6.624 / 6.880 / 6.304 /
// 6.624 / 6.656 us across five consecutive rounds (R6-R10): same-artifact
// bench noise is +/-0.3us around a ~6.6us graph-replay/launch floor. The
// warm kernel body is ~0.3us (one vectorized index-load round -> one
// fully-overlapped data-dependent gather round -> ~150cyc reduction tail),
// i.e. SMALLER than the bench's same-binary standard deviation — no
// in-kernel change can produce a measurable delta. All ncu pipes <=0.2%
// across ten profiles; useful traffic is 4KB, so no hardware roofline
// applies. Key algebraic insight (R1): the mask selects exactly one
// timestep per row and mask.sum()==B, so only 512 of the 131M input floats
// are ever read.
//
// 4 warps x 4 rows/thread:
//  - length/target read as one int4 per array per thread.
//  - 4 independent gathers per thread; all 512 gathers overlap in a single
//    L2/DRAM latency round chip-wide (irreducible: data-dependent addresses).
//  - Reduction: 3 register adds -> 5 warp shuffles -> 4 smem words -> one
//    thread does 3 adds + negate-scale multiply + store.

#define B_DIM 512
#define T_DIM 128
#define C_DIM 2000
#define NTHREADS 128
#define RPT 4   // rows per thread = B_DIM / NTHREADS
#define NWARPS (NTHREADS / 32)

__global__ __launch_bounds__(NTHREADS, 1)
void nll_seq_loss_kernel(const float* __restrict__ inputs,
                         const int*   __restrict__ length,
                         const int*   __restrict__ target,
                         float*       __restrict__ out) {
    const int t = threadIdx.x;
    const int base = t * RPT;   // contiguous 4-row chunk -> aligned int4

    int4 l = *(const int4*)(length + base);
    int4 g = *(const int4*)(target + base);

    int len[RPT] = {l.x, l.y, l.z, l.w};
    int tgt[RPT] = {g.x, g.y, g.z, g.w};

    float v[RPT];
    #pragma unroll
    for (int j = 0; j < RPT; j++) {
        int last = (len[j] < T_DIM ? len[j] : T_DIM) - 1;
        int idx = ((base + j) * T_DIM + last) * C_DIM + tgt[j];
        v[j] = __ldg(inputs + idx);
    }

    float s = (v[0] + v[1]) + (v[2] + v[3]);

    #pragma unroll
    for (int off = 16; off > 0; off >>= 1)
        s += __shfl_down_sync(0xFFFFFFFFu, s, off);

    __shared__ float warp_sums[NWARPS];
    const int lane = t & 31;
    const int wid  = t >> 5;
    if (lane == 0) warp_sums[wid] = s;
    __syncthreads();

    if (t == 0) {
        float w = (warp_sums[0] + warp_sums[1]) + (warp_sums[2] + warp_sums[3]);
        out[0] = w * (-1.0f / (float)B_DIM);
    }
}

extern "C" void kernel_launch(void* const* d_in, const int* in_sizes, int n_in,
                              void* d_out, int out_size) {
    const float* inputs = (const float*)d_in[0];
    const int*   length = (const int*)d_in[1];
    const int*   target = (const int*)d_in[2];
    float*       out    = (float*)d_out;

    nll_seq_loss_kernel<<<1, NTHREADS>>>(inputs, length, target, out);
}